// round 14
// baseline (speedup 1.0000x reference)
#include <cuda_runtime.h>
#include <cuda_bf16.h>

#define NJ 24
#define EPSF 1e-6f

typedef unsigned long long ull;

__device__ __forceinline__ ull f2_fma(ull a, ull b, ull c) {
    ull d; asm("fma.rn.f32x2 %0, %1, %2, %3;" : "=l"(d) : "l"(a), "l"(b), "l"(c)); return d;
}
__device__ __forceinline__ ull f2_mul(ull a, ull b) {
    ull d; asm("mul.rn.f32x2 %0, %1, %2;" : "=l"(d) : "l"(a), "l"(b)); return d;
}
__device__ __forceinline__ ull f2_add(ull a, ull b) {
    ull d; asm("add.rn.f32x2 %0, %1, %2;" : "=l"(d) : "l"(a), "l"(b)); return d;
}
__device__ __forceinline__ ull f2_pack(float lo, float hi) {
    ull d;
    asm("mov.b64 %0, {%1, %2};" : "=l"(d) : "r"(__float_as_uint(lo)), "r"(__float_as_uint(hi)));
    return d;
}
__device__ __forceinline__ void f2_unpack(ull a, float& lo, float& hi) {
    unsigned int l, h;
    asm("mov.b64 {%0, %1}, %2;" : "=r"(l), "=r"(h) : "l"(a));
    lo = __uint_as_float(l); hi = __uint_as_float(h);
}
__device__ __forceinline__ float sqrt_ap(float x) {
    float r; asm("sqrt.approx.f32 %0, %1;" : "=f"(r) : "f"(x)); return r;
}
__device__ __forceinline__ float rcp_ap(float x) {
    float r; asm("rcp.approx.f32 %0, %1;" : "=f"(r) : "f"(x)); return r;
}

// Per-joint constants, duplicated {v,v} pairs, 18 ulonglong2 per joint:
//  0 G00|G11   1 G22|2G01  2 2G02|2G12  3 bn0|bn1  4 bn2|cn      (n2 form)
//  5 P00|P11   6 P22|2P01  7 2P02|2P12  8 bP0|bP1  9 bP2|cP      (P form = a0'*n2form + Qform)
// 10 lL0|lL1  11 lL2|eL                                           (L form)
// 12 R00|R01  13 R02|R10  14 R11|R12  15 R20|R21  16 R22|tr0  17 tr1|tr2

__global__ __launch_bounds__(256, 4)
void shCaster_kernel(const float* __restrict__ xyz,
                     const float* __restrict__ vdir,
                     const float* __restrict__ transforms,
                     const float* __restrict__ sh_feats,
                     const float* __restrict__ locs,
                     float* __restrict__ out,
                     int half, int n)
{
    __shared__ __align__(16) ull SA[NJ * 36];

    if (threadIdx.x < NJ) {
        const int j = threadIdx.x;
        const float C0c = 0.28209479177387814f;
        const float C1c = 0.4886025119029199f;
        const float Bc  = 1.0925484305920792f;
        const float Cc  = 0.31539156525252005f;
        const float Dc  = 0.5462742152960396f;

        float R[3][3], trv[3], e[3];
        #pragma unroll
        for (int r = 0; r < 3; ++r) {
            #pragma unroll
            for (int c = 0; c < 3; ++c) R[r][c] = transforms[j * 16 + r * 4 + c];
            trv[r] = transforms[j * 16 + r * 4 + 3];
        }
        #pragma unroll
        for (int i = 0; i < 3; ++i) e[i] = locs[j * 3 + i] - trv[i];

        float f[9];
        #pragma unroll
        for (int k = 0; k < 9; ++k) f[k] = sh_feats[j * 9 + k];

        float a0p = C0c * f[0] + 0.5f - Cc * f[6];
        float aL[3] = { -C1c * f[3], -C1c * f[1], C1c * f[2] };   // on (dx,dy,dz)
        float a4 = Bc * f[4], a5 = -Bc * f[5], a7 = -Bc * f[7], a8 = Dc * f[8];
        float b6 = 3.0f * Cc * f[6];

        float H[3][3];
        H[0][0] = a8;  H[1][1] = -a8;  H[2][2] = b6;
        H[0][1] = H[1][0] = 0.5f * a4;
        H[1][2] = H[2][1] = 0.5f * a5;
        H[0][2] = H[2][0] = 0.5f * a7;

        float G[3][3], HR[3][3], M2[3][3], he[3];
        #pragma unroll
        for (int a = 0; a < 3; ++a)
            #pragma unroll
            for (int b = 0; b < 3; ++b) {
                float s = 0.f;
                #pragma unroll
                for (int i = 0; i < 3; ++i) s += R[i][a] * R[i][b];
                G[a][b] = s;
            }
        #pragma unroll
        for (int i = 0; i < 3; ++i) {
            #pragma unroll
            for (int c = 0; c < 3; ++c) {
                float s = 0.f;
                #pragma unroll
                for (int k = 0; k < 3; ++k) s += H[i][k] * R[k][c];
                HR[i][c] = s;
            }
            float sv = 0.f;
            #pragma unroll
            for (int k = 0; k < 3; ++k) sv += H[i][k] * e[k];
            he[i] = sv;
        }
        #pragma unroll
        for (int a = 0; a < 3; ++a)
            #pragma unroll
            for (int b = 0; b < 3; ++b) {
                float s = 0.f;
                #pragma unroll
                for (int i = 0; i < 3; ++i) s += R[i][a] * HR[i][b];
                M2[a][b] = s;
            }

        float bn[3], bQ[3], lL[3];
        #pragma unroll
        for (int a = 0; a < 3; ++a) {
            bn[a] = -2.f * (R[0][a] * e[0] + R[1][a] * e[1] + R[2][a] * e[2]);
            bQ[a] = -2.f * (he[0] * R[0][a] + he[1] * R[1][a] + he[2] * R[2][a]);
            lL[a] = -(aL[0] * R[0][a] + aL[1] * R[1][a] + aL[2] * R[2][a]);
        }
        float cn = e[0]*e[0] + e[1]*e[1] + e[2]*e[2];
        float cQ = e[0]*he[0] + e[1]*he[1] + e[2]*he[2];
        float eL = aL[0]*e[0] + aL[1]*e[1] + aL[2]*e[2];

        float av[36];
        av[0] = G[0][0];       av[1] = G[1][1];
        av[2] = G[2][2];       av[3] = 2.f*G[0][1];
        av[4] = 2.f*G[0][2];   av[5] = 2.f*G[1][2];
        av[6] = bn[0];         av[7] = bn[1];
        av[8] = bn[2];         av[9] = cn;
        av[10] = a0p*G[0][0] + M2[0][0];       av[11] = a0p*G[1][1] + M2[1][1];
        av[12] = a0p*G[2][2] + M2[2][2];       av[13] = 2.f*(a0p*G[0][1] + M2[0][1]);
        av[14] = 2.f*(a0p*G[0][2] + M2[0][2]); av[15] = 2.f*(a0p*G[1][2] + M2[1][2]);
        av[16] = a0p*bn[0] + bQ[0];            av[17] = a0p*bn[1] + bQ[1];
        av[18] = a0p*bn[2] + bQ[2];            av[19] = a0p*cn + cQ;
        av[20] = lL[0];  av[21] = lL[1];  av[22] = lL[2];  av[23] = eL;
        av[24] = R[0][0]; av[25] = R[0][1]; av[26] = R[0][2]; av[27] = R[1][0];
        av[28] = R[1][1]; av[29] = R[1][2]; av[30] = R[2][0]; av[31] = R[2][1];
        av[32] = R[2][2]; av[33] = trv[0]; av[34] = trv[1]; av[35] = trv[2];

        #pragma unroll
        for (int k = 0; k < 36; ++k) {
            unsigned int b = __float_as_uint(av[k]);
            SA[j * 36 + k] = ((ull)b << 32) | b;
        }
    }
    __syncthreads();

    int t = blockIdx.x * blockDim.x + threadIdx.x;
    if (t >= half) return;
    int i0 = t, i1 = t + half;

    const ull X = f2_pack(__ldg(&xyz[3 * i0]),     __ldg(&xyz[3 * i1]));
    const ull Y = f2_pack(__ldg(&xyz[3 * i0 + 1]), __ldg(&xyz[3 * i1 + 1]));
    const ull Z = f2_pack(__ldg(&xyz[3 * i0 + 2]), __ldg(&xyz[3 * i1 + 2]));

    const ull XX = f2_mul(X, X);
    const ull YY = f2_mul(Y, Y);
    const ull ZZ = f2_mul(Z, Z);
    const ull XY = f2_mul(X, Y);
    const ull XZ = f2_mul(X, Z);
    const ull YZ = f2_mul(Y, Z);

    const ull NEG1 = f2_pack(-1.f, -1.f);

    ull wsum2 = 0ull;
    ull t00 = 0ull, t01 = 0ull, t02 = 0ull, t03 = 0ull;
    ull t10 = 0ull, t11 = 0ull, t12 = 0ull, t13 = 0ull;
    ull t20 = 0ull, t21 = 0ull, t22 = 0ull, t23 = 0ull;

#pragma unroll 4
    for (int j = 0; j < NJ; ++j) {
        const ulonglong2* C = reinterpret_cast<const ulonglong2*>(SA + j * 36);
        const ulonglong2 A0 = C[0],  A1 = C[1],  A2 = C[2],  A3 = C[3],  A4 = C[4];
        const ulonglong2 A5 = C[5],  A6 = C[6],  A7 = C[7],  A8 = C[8],  A9 = C[9];
        const ulonglong2 AA = C[10], AB = C[11];

        // n2(x), P(x), L(x)
        ull n2 = f2_fma(A0.x, XX, f2_fma(A0.y, YY, f2_fma(A1.x, ZZ,
                 f2_fma(A1.y, XY, f2_fma(A2.x, XZ, f2_fma(A2.y, YZ,
                 f2_fma(A3.x, X,  f2_fma(A3.y, Y,  f2_fma(A4.x, Z, A4.y)))))))));
        ull P  = f2_fma(A5.x, XX, f2_fma(A5.y, YY, f2_fma(A6.x, ZZ,
                 f2_fma(A6.y, XY, f2_fma(A7.x, XZ, f2_fma(A7.y, YZ,
                 f2_fma(A8.x, X,  f2_fma(A8.y, Y,  f2_fma(A9.x, Z, A9.y)))))))));
        ull L  = f2_fma(AA.x, X, f2_fma(AA.y, Y, f2_fma(AB.x, Z, AB.y)));

        // per-lane sqrt
        float n2a, n2b; f2_unpack(n2, n2a, n2b);
        n2a = fmaxf(n2a, 0.f); n2b = fmaxf(n2b, 0.f);
        ull s2 = f2_pack(sqrt_ap(n2a), sqrt_ap(n2b));
        ull n2c = f2_pack(n2a, n2b);

        ull denom = f2_fma(L, s2, P);              // rad * n2
        ull u  = f2_fma(n2c, NEG1, L);             // L - n2
        ull tt = f2_fma(u, s2, P);                 // denom - numer

        float ta, tb; f2_unpack(tt, ta, tb);
        float da, db; f2_unpack(denom, da, db);
        float wa = fmaxf(ta, 0.f) * rcp_ap(fmaxf(da, 1e-30f));
        float wb = fmaxf(tb, 0.f) * rcp_ap(fmaxf(db, 1e-30f));
        ull w2 = f2_pack(wa, wb);

        const ulonglong2 B0 = C[12], B1 = C[13], B2 = C[14];
        const ulonglong2 B3 = C[15], B4 = C[16], B5 = C[17];

        wsum2 = f2_add(wsum2, w2);
        t00 = f2_fma(w2, B0.x, t00);
        t01 = f2_fma(w2, B0.y, t01);
        t02 = f2_fma(w2, B1.x, t02);
        t10 = f2_fma(w2, B1.y, t10);
        t11 = f2_fma(w2, B2.x, t11);
        t12 = f2_fma(w2, B2.y, t12);
        t20 = f2_fma(w2, B3.x, t20);
        t21 = f2_fma(w2, B3.y, t21);
        t22 = f2_fma(w2, B4.x, t22);
        t03 = f2_fma(w2, B4.y, t03);
        t13 = f2_fma(w2, B5.x, t13);
        t23 = f2_fma(w2, B5.y, t23);
    }

    // ---- epilogue per lane ----
    const float vxa = __ldg(&vdir[3 * i0]),     vxb = __ldg(&vdir[3 * i1]);
    const float vya = __ldg(&vdir[3 * i0 + 1]), vyb = __ldg(&vdir[3 * i1 + 1]);
    const float vza = __ldg(&vdir[3 * i0 + 2]), vzb = __ldg(&vdir[3 * i1 + 2]);

    float wsa, wsb; f2_unpack(wsum2, wsa, wsb);
    float a00, b00; f2_unpack(t00, a00, b00);
    float a01, b01; f2_unpack(t01, a01, b01);
    float a02, b02; f2_unpack(t02, a02, b02);
    float a03, b03; f2_unpack(t03, a03, b03);
    float a10, b10; f2_unpack(t10, a10, b10);
    float a11, b11; f2_unpack(t11, a11, b11);
    float a12, b12; f2_unpack(t12, a12, b12);
    float a13, b13; f2_unpack(t13, a13, b13);
    float a20, b20; f2_unpack(t20, a20, b20);
    float a21, b21; f2_unpack(t21, a21, b21);
    float a22, b22; f2_unpack(t22, a22, b22);
    float a23, b23; f2_unpack(t23, a23, b23);

    float xa, xb, ya, yb, za, zb;
    f2_unpack(X, xa, xb); f2_unpack(Y, ya, yb); f2_unpack(Z, za, zb);

    float* outv = out + (size_t)3 * n;

    if (wsa > EPSF) {
        float inv = rcp_ap(wsa);
        out[3 * i0]     = fmaf(a00, xa, fmaf(a01, ya, fmaf(a02, za, a03))) * inv;
        out[3 * i0 + 1] = fmaf(a10, xa, fmaf(a11, ya, fmaf(a12, za, a13))) * inv;
        out[3 * i0 + 2] = fmaf(a20, xa, fmaf(a21, ya, fmaf(a22, za, a23))) * inv;
        outv[3 * i0]     = fmaf(a00, vxa, fmaf(a01, vya, a02 * vza)) * inv;
        outv[3 * i0 + 1] = fmaf(a10, vxa, fmaf(a11, vya, a12 * vza)) * inv;
        outv[3 * i0 + 2] = fmaf(a20, vxa, fmaf(a21, vya, a22 * vza)) * inv;
    } else {
        out[3 * i0] = xa;  out[3 * i0 + 1] = ya;  out[3 * i0 + 2] = za;
        outv[3 * i0] = vxa; outv[3 * i0 + 1] = vya; outv[3 * i0 + 2] = vza;
    }
    if (wsb > EPSF) {
        float inv = rcp_ap(wsb);
        out[3 * i1]     = fmaf(b00, xb, fmaf(b01, yb, fmaf(b02, zb, b03))) * inv;
        out[3 * i1 + 1] = fmaf(b10, xb, fmaf(b11, yb, fmaf(b12, zb, b13))) * inv;
        out[3 * i1 + 2] = fmaf(b20, xb, fmaf(b21, yb, fmaf(b22, zb, b23))) * inv;
        outv[3 * i1]     = fmaf(b00, vxb, fmaf(b01, vyb, b02 * vzb)) * inv;
        outv[3 * i1 + 1] = fmaf(b10, vxb, fmaf(b11, vyb, b12 * vzb)) * inv;
        outv[3 * i1 + 2] = fmaf(b20, vxb, fmaf(b21, vyb, b22 * vzb)) * inv;
    } else {
        out[3 * i1] = xb;  out[3 * i1 + 1] = yb;  out[3 * i1 + 2] = zb;
        outv[3 * i1] = vxb; outv[3 * i1 + 1] = vyb; outv[3 * i1 + 2] = vzb;
    }
}

extern "C" void kernel_launch(void* const* d_in, const int* in_sizes, int n_in,
                              void* d_out, int out_size) {
    const float* xyz        = (const float*)d_in[0];
    const float* viewdirs   = (const float*)d_in[1];
    const float* transforms = (const float*)d_in[2];
    // d_in[3] = ray_valid — unused
    const float* sh_feats   = (const float*)d_in[4];
    const float* locs       = (const float*)d_in[5];
    float* out = (float*)d_out;

    int n = in_sizes[0] / 3;      // 524288
    int half = n / 2;             // 262144
    int threads = 256;
    int blocks = (half + threads - 1) / threads;
    shCaster_kernel<<<blocks, threads>>>(xyz, viewdirs, transforms, sh_feats,
                                         locs, out, half, n);
}

// round 15
// speedup vs baseline: 1.1299x; 1.1299x over previous
#include <cuda_runtime.h>
#include <cuda_bf16.h>

#define NJ 24
#define EPSF 1e-6f

__device__ __forceinline__ float sqrt_ap(float x) {
    float r; asm("sqrt.approx.f32 %0, %1;" : "=f"(r) : "f"(x)); return r;
}
__device__ __forceinline__ float rcp_ap(float x) {
    float r; asm("rcp.approx.f32 %0, %1;" : "=f"(r) : "f"(x)); return r;
}

// Per-joint constants: 9 float4 (36 unique floats):
// q0 {G00,G11,G22,2G01}  q1 {2G02,2G12,bn0,bn1}  q2 {bn2,cn,P00,P11}
// q3 {P22,2P01,2P02,2P12} q4 {bP0,bP1,bP2,cP}    q5 {lL0,lL1,lL2,eL}
// q6 {R00,R01,R02,R10}   q7 {R11,R12,R20,R21}    q8 {R22,tr0,tr1,tr2}
// where n2(x)=xGx+bn.x+cn, P = a0'*n2form + Qform, L linear; outputs via T=Σw[R|tr].

__global__ __launch_bounds__(256, 3)
void shCaster_kernel(const float* __restrict__ xyz,
                     const float* __restrict__ vdir,
                     const float* __restrict__ transforms,
                     const float* __restrict__ sh_feats,
                     const float* __restrict__ locs,
                     float* __restrict__ out,
                     int half, int n)
{
    __shared__ __align__(16) float4 S[NJ * 9];

    if (threadIdx.x < NJ) {
        const int j = threadIdx.x;
        const float C0c = 0.28209479177387814f;
        const float C1c = 0.4886025119029199f;
        const float Bc  = 1.0925484305920792f;
        const float Cc  = 0.31539156525252005f;
        const float Dc  = 0.5462742152960396f;

        float R[3][3], trv[3], e[3];
        #pragma unroll
        for (int r = 0; r < 3; ++r) {
            #pragma unroll
            for (int c = 0; c < 3; ++c) R[r][c] = transforms[j * 16 + r * 4 + c];
            trv[r] = transforms[j * 16 + r * 4 + 3];
        }
        #pragma unroll
        for (int i = 0; i < 3; ++i) e[i] = locs[j * 3 + i] - trv[i];

        float f[9];
        #pragma unroll
        for (int k = 0; k < 9; ++k) f[k] = sh_feats[j * 9 + k];

        float a0p = C0c * f[0] + 0.5f - Cc * f[6];
        float aL[3] = { -C1c * f[3], -C1c * f[1], C1c * f[2] };
        float a4 = Bc * f[4], a5 = -Bc * f[5], a7 = -Bc * f[7], a8 = Dc * f[8];
        float b6 = 3.0f * Cc * f[6];

        float H[3][3];
        H[0][0] = a8;  H[1][1] = -a8;  H[2][2] = b6;
        H[0][1] = H[1][0] = 0.5f * a4;
        H[1][2] = H[2][1] = 0.5f * a5;
        H[0][2] = H[2][0] = 0.5f * a7;

        float G[3][3], HR[3][3], M2[3][3], he[3];
        #pragma unroll
        for (int a = 0; a < 3; ++a)
            #pragma unroll
            for (int b = 0; b < 3; ++b) {
                float s = 0.f;
                #pragma unroll
                for (int i = 0; i < 3; ++i) s += R[i][a] * R[i][b];
                G[a][b] = s;
            }
        #pragma unroll
        for (int i = 0; i < 3; ++i) {
            #pragma unroll
            for (int c = 0; c < 3; ++c) {
                float s = 0.f;
                #pragma unroll
                for (int k = 0; k < 3; ++k) s += H[i][k] * R[k][c];
                HR[i][c] = s;
            }
            float sv = 0.f;
            #pragma unroll
            for (int k = 0; k < 3; ++k) sv += H[i][k] * e[k];
            he[i] = sv;
        }
        #pragma unroll
        for (int a = 0; a < 3; ++a)
            #pragma unroll
            for (int b = 0; b < 3; ++b) {
                float s = 0.f;
                #pragma unroll
                for (int i = 0; i < 3; ++i) s += R[i][a] * HR[i][b];
                M2[a][b] = s;
            }

        float bn[3], bQ[3], lL[3];
        #pragma unroll
        for (int a = 0; a < 3; ++a) {
            bn[a] = -2.f * (R[0][a] * e[0] + R[1][a] * e[1] + R[2][a] * e[2]);
            bQ[a] = -2.f * (he[0] * R[0][a] + he[1] * R[1][a] + he[2] * R[2][a]);
            lL[a] = -(aL[0] * R[0][a] + aL[1] * R[1][a] + aL[2] * R[2][a]);
        }
        float cn = e[0]*e[0] + e[1]*e[1] + e[2]*e[2];
        float cQ = e[0]*he[0] + e[1]*he[1] + e[2]*he[2];
        float eL = aL[0]*e[0] + aL[1]*e[1] + aL[2]*e[2];

        S[j*9+0] = make_float4(G[0][0], G[1][1], G[2][2], 2.f*G[0][1]);
        S[j*9+1] = make_float4(2.f*G[0][2], 2.f*G[1][2], bn[0], bn[1]);
        S[j*9+2] = make_float4(bn[2], cn,
                               a0p*G[0][0] + M2[0][0], a0p*G[1][1] + M2[1][1]);
        S[j*9+3] = make_float4(a0p*G[2][2] + M2[2][2],
                               2.f*(a0p*G[0][1] + M2[0][1]),
                               2.f*(a0p*G[0][2] + M2[0][2]),
                               2.f*(a0p*G[1][2] + M2[1][2]));
        S[j*9+4] = make_float4(a0p*bn[0] + bQ[0], a0p*bn[1] + bQ[1],
                               a0p*bn[2] + bQ[2], a0p*cn + cQ);
        S[j*9+5] = make_float4(lL[0], lL[1], lL[2], eL);
        S[j*9+6] = make_float4(R[0][0], R[0][1], R[0][2], R[1][0]);
        S[j*9+7] = make_float4(R[1][1], R[1][2], R[2][0], R[2][1]);
        S[j*9+8] = make_float4(R[2][2], trv[0], trv[1], trv[2]);
    }
    __syncthreads();

    int t = blockIdx.x * blockDim.x + threadIdx.x;
    if (t >= half) return;
    int i0 = t, i1 = t + half;

    const float xa = __ldg(&xyz[3*i0]), ya = __ldg(&xyz[3*i0+1]), za = __ldg(&xyz[3*i0+2]);
    const float xb = __ldg(&xyz[3*i1]), yb = __ldg(&xyz[3*i1+1]), zb = __ldg(&xyz[3*i1+2]);

    const float xxa = xa*xa, yya = ya*ya, zza = za*za;
    const float xya = xa*ya, xza = xa*za, yza = ya*za;
    const float xxb = xb*xb, yyb = yb*yb, zzb = zb*zb;
    const float xyb = xb*yb, xzb = xb*zb, yzb = yb*zb;

    float wsa = 0.f, wsb = 0.f;
    float a00=0.f,a01=0.f,a02=0.f,a03=0.f, a10=0.f,a11=0.f,a12=0.f,a13=0.f;
    float a20=0.f,a21=0.f,a22=0.f,a23=0.f;
    float b00=0.f,b01=0.f,b02=0.f,b03=0.f, b10=0.f,b11=0.f,b12=0.f,b13=0.f;
    float b20=0.f,b21=0.f,b22=0.f,b23=0.f;

#pragma unroll 1
    for (int j = 0; j < NJ; ++j) {
        const float4* q = &S[j * 9];
        const float4 q0 = q[0], q1 = q[1], q2 = q[2];
        const float4 q3 = q[3], q4 = q[4], q5 = q[5];

        float n2a = fmaf(q0.x,xxa, fmaf(q0.y,yya, fmaf(q0.z,zza,
                    fmaf(q0.w,xya, fmaf(q1.x,xza, fmaf(q1.y,yza,
                    fmaf(q1.z,xa,  fmaf(q1.w,ya,  fmaf(q2.x,za, q2.y)))))))));
        float n2b = fmaf(q0.x,xxb, fmaf(q0.y,yyb, fmaf(q0.z,zzb,
                    fmaf(q0.w,xyb, fmaf(q1.x,xzb, fmaf(q1.y,yzb,
                    fmaf(q1.z,xb,  fmaf(q1.w,yb,  fmaf(q2.x,zb, q2.y)))))))));
        float Pa  = fmaf(q2.z,xxa, fmaf(q2.w,yya, fmaf(q3.x,zza,
                    fmaf(q3.y,xya, fmaf(q3.z,xza, fmaf(q3.w,yza,
                    fmaf(q4.x,xa,  fmaf(q4.y,ya,  fmaf(q4.z,za, q4.w)))))))));
        float Pb  = fmaf(q2.z,xxb, fmaf(q2.w,yyb, fmaf(q3.x,zzb,
                    fmaf(q3.y,xyb, fmaf(q3.z,xzb, fmaf(q3.w,yzb,
                    fmaf(q4.x,xb,  fmaf(q4.y,yb,  fmaf(q4.z,zb, q4.w)))))))));
        float La  = fmaf(q5.x,xa, fmaf(q5.y,ya, fmaf(q5.z,za, q5.w)));
        float Lb  = fmaf(q5.x,xb, fmaf(q5.y,yb, fmaf(q5.z,zb, q5.w)));

        n2a = fmaxf(n2a, 0.f);
        n2b = fmaxf(n2b, 0.f);
        float sa = sqrt_ap(n2a), sb = sqrt_ap(n2b);
        float dena = fmaf(La, sa, Pa), denb = fmaf(Lb, sb, Pb);
        float tta = fmaf(La - n2a, sa, Pa), ttb = fmaf(Lb - n2b, sb, Pb);
        float wa = fmaxf(tta, 0.f) * rcp_ap(fmaxf(dena, 1e-30f));
        float wb = fmaxf(ttb, 0.f) * rcp_ap(fmaxf(denb, 1e-30f));

        const float4 q6 = q[6], q7 = q[7], q8 = q[8];
        wsa += wa;                      wsb += wb;
        a00 = fmaf(wa, q6.x, a00);      b00 = fmaf(wb, q6.x, b00);
        a01 = fmaf(wa, q6.y, a01);      b01 = fmaf(wb, q6.y, b01);
        a02 = fmaf(wa, q6.z, a02);      b02 = fmaf(wb, q6.z, b02);
        a10 = fmaf(wa, q6.w, a10);      b10 = fmaf(wb, q6.w, b10);
        a11 = fmaf(wa, q7.x, a11);      b11 = fmaf(wb, q7.x, b11);
        a12 = fmaf(wa, q7.y, a12);      b12 = fmaf(wb, q7.y, b12);
        a20 = fmaf(wa, q7.z, a20);      b20 = fmaf(wb, q7.z, b20);
        a21 = fmaf(wa, q7.w, a21);      b21 = fmaf(wb, q7.w, b21);
        a22 = fmaf(wa, q8.x, a22);      b22 = fmaf(wb, q8.x, b22);
        a03 = fmaf(wa, q8.y, a03);      b03 = fmaf(wb, q8.y, b03);
        a13 = fmaf(wa, q8.z, a13);      b13 = fmaf(wb, q8.z, b13);
        a23 = fmaf(wa, q8.w, a23);      b23 = fmaf(wb, q8.w, b23);
    }

    // ---- epilogue ----
    const float vxa = __ldg(&vdir[3*i0]), vya = __ldg(&vdir[3*i0+1]), vza = __ldg(&vdir[3*i0+2]);
    const float vxb = __ldg(&vdir[3*i1]), vyb = __ldg(&vdir[3*i1+1]), vzb = __ldg(&vdir[3*i1+2]);

    float* outv = out + (size_t)3 * n;

    if (wsa > EPSF) {
        float inv = rcp_ap(wsa);
        out[3*i0]   = fmaf(a00, xa, fmaf(a01, ya, fmaf(a02, za, a03))) * inv;
        out[3*i0+1] = fmaf(a10, xa, fmaf(a11, ya, fmaf(a12, za, a13))) * inv;
        out[3*i0+2] = fmaf(a20, xa, fmaf(a21, ya, fmaf(a22, za, a23))) * inv;
        outv[3*i0]   = fmaf(a00, vxa, fmaf(a01, vya, a02 * vza)) * inv;
        outv[3*i0+1] = fmaf(a10, vxa, fmaf(a11, vya, a12 * vza)) * inv;
        outv[3*i0+2] = fmaf(a20, vxa, fmaf(a21, vya, a22 * vza)) * inv;
    } else {
        out[3*i0] = xa;  out[3*i0+1] = ya;  out[3*i0+2] = za;
        outv[3*i0] = vxa; outv[3*i0+1] = vya; outv[3*i0+2] = vza;
    }
    if (wsb > EPSF) {
        float inv = rcp_ap(wsb);
        out[3*i1]   = fmaf(b00, xb, fmaf(b01, yb, fmaf(b02, zb, b03))) * inv;
        out[3*i1+1] = fmaf(b10, xb, fmaf(b11, yb, fmaf(b12, zb, b13))) * inv;
        out[3*i1+2] = fmaf(b20, xb, fmaf(b21, yb, fmaf(b22, zb, b23))) * inv;
        outv[3*i1]   = fmaf(b00, vxb, fmaf(b01, vyb, b02 * vzb)) * inv;
        outv[3*i1+1] = fmaf(b10, vxb, fmaf(b11, vyb, b12 * vzb)) * inv;
        outv[3*i1+2] = fmaf(b20, vxb, fmaf(b21, vyb, b22 * vzb)) * inv;
    } else {
        out[3*i1] = xb;  out[3*i1+1] = yb;  out[3*i1+2] = zb;
        outv[3*i1] = vxb; outv[3*i1+1] = vyb; outv[3*i1+2] = vzb;
    }
}

extern "C" void kernel_launch(void* const* d_in, const int* in_sizes, int n_in,
                              void* d_out, int out_size) {
    const float* xyz        = (const float*)d_in[0];
    const float* viewdirs   = (const float*)d_in[1];
    const float* transforms = (const float*)d_in[2];
    // d_in[3] = ray_valid — unused
    const float* sh_feats   = (const float*)d_in[4];
    const float* locs       = (const float*)d_in[5];
    float* out = (float*)d_out;

    int n = in_sizes[0] / 3;      // 524288
    int half = n / 2;             // 262144
    int threads = 256;
    int blocks = (half + threads - 1) / threads;
    shCaster_kernel<<<blocks, threads>>>(xyz, viewdirs, transforms, sh_feats,
                                         locs, out, half, n);
}

// round 16
// speedup vs baseline: 1.1578x; 1.0247x over previous
#include <cuda_runtime.h>
#include <cuda_bf16.h>

#define NJ 24
#define EPSF 1e-6f

__device__ __forceinline__ float sqrt_ap(float x) {
    float r; asm("sqrt.approx.f32 %0, %1;" : "=f"(r) : "f"(x)); return r;
}
__device__ __forceinline__ float rcp_ap(float x) {
    float r; asm("rcp.approx.f32 %0, %1;" : "=f"(r) : "f"(x)); return r;
}

// Per-joint constants: 9 float4 (36 unique floats):
// q0 {G00,G11,G22,2G01}  q1 {2G02,2G12,bn0,bn1}  q2 {bn2,cn,P00,P11}
// q3 {P22,2P01,2P02,2P12} q4 {bP0,bP1,bP2,cP}    q5 {lL0,lL1,lL2,eL}
// q6 {R00,R01,R02,R10}   q7 {R11,R12,R20,R21}    q8 {R22,tr0,tr1,tr2}
// n2(x)=xGx+bn.x+cn, P = a0'*n2form + Qform, L linear; outputs via T=Σw[R|tr].

__global__ __launch_bounds__(256, 4)     // force <=64 regs -> 4 CTAs/SM
void shCaster_kernel(const float* __restrict__ xyz,
                     const float* __restrict__ vdir,
                     const float* __restrict__ transforms,
                     const float* __restrict__ sh_feats,
                     const float* __restrict__ locs,
                     float* __restrict__ out,
                     int half, int n)
{
    __shared__ __align__(16) float4 S[NJ * 9];

    if (threadIdx.x < NJ) {
        const int j = threadIdx.x;
        const float C0c = 0.28209479177387814f;
        const float C1c = 0.4886025119029199f;
        const float Bc  = 1.0925484305920792f;
        const float Cc  = 0.31539156525252005f;
        const float Dc  = 0.5462742152960396f;

        float R[3][3], trv[3], e[3];
        #pragma unroll
        for (int r = 0; r < 3; ++r) {
            #pragma unroll
            for (int c = 0; c < 3; ++c) R[r][c] = transforms[j * 16 + r * 4 + c];
            trv[r] = transforms[j * 16 + r * 4 + 3];
        }
        #pragma unroll
        for (int i = 0; i < 3; ++i) e[i] = locs[j * 3 + i] - trv[i];

        float f[9];
        #pragma unroll
        for (int k = 0; k < 9; ++k) f[k] = sh_feats[j * 9 + k];

        float a0p = C0c * f[0] + 0.5f - Cc * f[6];
        float aL[3] = { -C1c * f[3], -C1c * f[1], C1c * f[2] };
        float a4 = Bc * f[4], a5 = -Bc * f[5], a7 = -Bc * f[7], a8 = Dc * f[8];
        float b6 = 3.0f * Cc * f[6];

        float H[3][3];
        H[0][0] = a8;  H[1][1] = -a8;  H[2][2] = b6;
        H[0][1] = H[1][0] = 0.5f * a4;
        H[1][2] = H[2][1] = 0.5f * a5;
        H[0][2] = H[2][0] = 0.5f * a7;

        float G[3][3], HR[3][3], M2[3][3], he[3];
        #pragma unroll
        for (int a = 0; a < 3; ++a)
            #pragma unroll
            for (int b = 0; b < 3; ++b) {
                float s = 0.f;
                #pragma unroll
                for (int i = 0; i < 3; ++i) s += R[i][a] * R[i][b];
                G[a][b] = s;
            }
        #pragma unroll
        for (int i = 0; i < 3; ++i) {
            #pragma unroll
            for (int c = 0; c < 3; ++c) {
                float s = 0.f;
                #pragma unroll
                for (int k = 0; k < 3; ++k) s += H[i][k] * R[k][c];
                HR[i][c] = s;
            }
            float sv = 0.f;
            #pragma unroll
            for (int k = 0; k < 3; ++k) sv += H[i][k] * e[k];
            he[i] = sv;
        }
        #pragma unroll
        for (int a = 0; a < 3; ++a)
            #pragma unroll
            for (int b = 0; b < 3; ++b) {
                float s = 0.f;
                #pragma unroll
                for (int i = 0; i < 3; ++i) s += R[i][a] * HR[i][b];
                M2[a][b] = s;
            }

        float bn[3], bQ[3], lL[3];
        #pragma unroll
        for (int a = 0; a < 3; ++a) {
            bn[a] = -2.f * (R[0][a] * e[0] + R[1][a] * e[1] + R[2][a] * e[2]);
            bQ[a] = -2.f * (he[0] * R[0][a] + he[1] * R[1][a] + he[2] * R[2][a]);
            lL[a] = -(aL[0] * R[0][a] + aL[1] * R[1][a] + aL[2] * R[2][a]);
        }
        float cn = e[0]*e[0] + e[1]*e[1] + e[2]*e[2];
        float cQ = e[0]*he[0] + e[1]*he[1] + e[2]*he[2];
        float eL = aL[0]*e[0] + aL[1]*e[1] + aL[2]*e[2];

        S[j*9+0] = make_float4(G[0][0], G[1][1], G[2][2], 2.f*G[0][1]);
        S[j*9+1] = make_float4(2.f*G[0][2], 2.f*G[1][2], bn[0], bn[1]);
        S[j*9+2] = make_float4(bn[2], cn,
                               a0p*G[0][0] + M2[0][0], a0p*G[1][1] + M2[1][1]);
        S[j*9+3] = make_float4(a0p*G[2][2] + M2[2][2],
                               2.f*(a0p*G[0][1] + M2[0][1]),
                               2.f*(a0p*G[0][2] + M2[0][2]),
                               2.f*(a0p*G[1][2] + M2[1][2]));
        S[j*9+4] = make_float4(a0p*bn[0] + bQ[0], a0p*bn[1] + bQ[1],
                               a0p*bn[2] + bQ[2], a0p*cn + cQ);
        S[j*9+5] = make_float4(lL[0], lL[1], lL[2], eL);
        S[j*9+6] = make_float4(R[0][0], R[0][1], R[0][2], R[1][0]);
        S[j*9+7] = make_float4(R[1][1], R[1][2], R[2][0], R[2][1]);
        S[j*9+8] = make_float4(R[2][2], trv[0], trv[1], trv[2]);
    }
    __syncthreads();

    int t = blockIdx.x * blockDim.x + threadIdx.x;
    if (t >= half) return;
    int i0 = t, i1 = t + half;

    const float xa = __ldg(&xyz[3*i0]), ya = __ldg(&xyz[3*i0+1]), za = __ldg(&xyz[3*i0+2]);
    const float xb = __ldg(&xyz[3*i1]), yb = __ldg(&xyz[3*i1+1]), zb = __ldg(&xyz[3*i1+2]);

    const float xxa = xa*xa, yya = ya*ya, zza = za*za;
    const float xya = xa*ya, xza = xa*za, yza = ya*za;
    const float xxb = xb*xb, yyb = yb*yb, zzb = zb*zb;
    const float xyb = xb*yb, xzb = xb*zb, yzb = yb*zb;

    float wsa = 0.f, wsb = 0.f;
    float a00=0.f,a01=0.f,a02=0.f,a03=0.f, a10=0.f,a11=0.f,a12=0.f,a13=0.f;
    float a20=0.f,a21=0.f,a22=0.f,a23=0.f;
    float b00=0.f,b01=0.f,b02=0.f,b03=0.f, b10=0.f,b11=0.f,b12=0.f,b13=0.f;
    float b20=0.f,b21=0.f,b22=0.f,b23=0.f;

#pragma unroll 1
    for (int j = 0; j < NJ; ++j) {
        const float4* q = &S[j * 9];
        const float4 q0 = q[0], q1 = q[1], q2 = q[2];
        const float4 q3 = q[3], q4 = q[4], q5 = q[5];

        float n2a = fmaf(q0.x,xxa, fmaf(q0.y,yya, fmaf(q0.z,zza,
                    fmaf(q0.w,xya, fmaf(q1.x,xza, fmaf(q1.y,yza,
                    fmaf(q1.z,xa,  fmaf(q1.w,ya,  fmaf(q2.x,za, q2.y)))))))));
        float n2b = fmaf(q0.x,xxb, fmaf(q0.y,yyb, fmaf(q0.z,zzb,
                    fmaf(q0.w,xyb, fmaf(q1.x,xzb, fmaf(q1.y,yzb,
                    fmaf(q1.z,xb,  fmaf(q1.w,yb,  fmaf(q2.x,zb, q2.y)))))))));
        float Pa  = fmaf(q2.z,xxa, fmaf(q2.w,yya, fmaf(q3.x,zza,
                    fmaf(q3.y,xya, fmaf(q3.z,xza, fmaf(q3.w,yza,
                    fmaf(q4.x,xa,  fmaf(q4.y,ya,  fmaf(q4.z,za, q4.w)))))))));
        float Pb  = fmaf(q2.z,xxb, fmaf(q2.w,yyb, fmaf(q3.x,zzb,
                    fmaf(q3.y,xyb, fmaf(q3.z,xzb, fmaf(q3.w,yzb,
                    fmaf(q4.x,xb,  fmaf(q4.y,yb,  fmaf(q4.z,zb, q4.w)))))))));
        float La  = fmaf(q5.x,xa, fmaf(q5.y,ya, fmaf(q5.z,za, q5.w)));
        float Lb  = fmaf(q5.x,xb, fmaf(q5.y,yb, fmaf(q5.z,zb, q5.w)));

        n2a = fmaxf(n2a, 0.f);
        n2b = fmaxf(n2b, 0.f);
        float sa = sqrt_ap(n2a), sb = sqrt_ap(n2b);
        float dena = fmaf(La, sa, Pa), denb = fmaf(Lb, sb, Pb);
        float tta = fmaf(La - n2a, sa, Pa), ttb = fmaf(Lb - n2b, sb, Pb);
        float wa = fmaxf(tta, 0.f) * rcp_ap(fmaxf(dena, 1e-30f));
        float wb = fmaxf(ttb, 0.f) * rcp_ap(fmaxf(denb, 1e-30f));

        const float4 q6 = q[6], q7 = q[7], q8 = q[8];
        wsa += wa;                      wsb += wb;
        a00 = fmaf(wa, q6.x, a00);      b00 = fmaf(wb, q6.x, b00);
        a01 = fmaf(wa, q6.y, a01);      b01 = fmaf(wb, q6.y, b01);
        a02 = fmaf(wa, q6.z, a02);      b02 = fmaf(wb, q6.z, b02);
        a10 = fmaf(wa, q6.w, a10);      b10 = fmaf(wb, q6.w, b10);
        a11 = fmaf(wa, q7.x, a11);      b11 = fmaf(wb, q7.x, b11);
        a12 = fmaf(wa, q7.y, a12);      b12 = fmaf(wb, q7.y, b12);
        a20 = fmaf(wa, q7.z, a20);      b20 = fmaf(wb, q7.z, b20);
        a21 = fmaf(wa, q7.w, a21);      b21 = fmaf(wb, q7.w, b21);
        a22 = fmaf(wa, q8.x, a22);      b22 = fmaf(wb, q8.x, b22);
        a03 = fmaf(wa, q8.y, a03);      b03 = fmaf(wb, q8.y, b03);
        a13 = fmaf(wa, q8.z, a13);      b13 = fmaf(wb, q8.z, b13);
        a23 = fmaf(wa, q8.w, a23);      b23 = fmaf(wb, q8.w, b23);
    }

    // ---- epilogue ----
    const float vxa = __ldg(&vdir[3*i0]), vya = __ldg(&vdir[3*i0+1]), vza = __ldg(&vdir[3*i0+2]);
    const float vxb = __ldg(&vdir[3*i1]), vyb = __ldg(&vdir[3*i1+1]), vzb = __ldg(&vdir[3*i1+2]);

    float* outv = out + (size_t)3 * n;

    if (wsa > EPSF) {
        float inv = rcp_ap(wsa);
        out[3*i0]   = fmaf(a00, xa, fmaf(a01, ya, fmaf(a02, za, a03))) * inv;
        out[3*i0+1] = fmaf(a10, xa, fmaf(a11, ya, fmaf(a12, za, a13))) * inv;
        out[3*i0+2] = fmaf(a20, xa, fmaf(a21, ya, fmaf(a22, za, a23))) * inv;
        outv[3*i0]   = fmaf(a00, vxa, fmaf(a01, vya, a02 * vza)) * inv;
        outv[3*i0+1] = fmaf(a10, vxa, fmaf(a11, vya, a12 * vza)) * inv;
        outv[3*i0+2] = fmaf(a20, vxa, fmaf(a21, vya, a22 * vza)) * inv;
    } else {
        out[3*i0] = xa;  out[3*i0+1] = ya;  out[3*i0+2] = za;
        outv[3*i0] = vxa; outv[3*i0+1] = vya; outv[3*i0+2] = vza;
    }
    if (wsb > EPSF) {
        float inv = rcp_ap(wsb);
        out[3*i1]   = fmaf(b00, xb, fmaf(b01, yb, fmaf(b02, zb, b03))) * inv;
        out[3*i1+1] = fmaf(b10, xb, fmaf(b11, yb, fmaf(b12, zb, b13))) * inv;
        out[3*i1+2] = fmaf(b20, xb, fmaf(b21, yb, fmaf(b22, zb, b23))) * inv;
        outv[3*i1]   = fmaf(b00, vxb, fmaf(b01, vyb, b02 * vzb)) * inv;
        outv[3*i1+1] = fmaf(b10, vxb, fmaf(b11, vyb, b12 * vzb)) * inv;
        outv[3*i1+2] = fmaf(b20, vxb, fmaf(b21, vyb, b22 * vzb)) * inv;
    } else {
        out[3*i1] = xb;  out[3*i1+1] = yb;  out[3*i1+2] = zb;
        outv[3*i1] = vxb; outv[3*i1+1] = vyb; outv[3*i1+2] = vzb;
    }
}

extern "C" void kernel_launch(void* const* d_in, const int* in_sizes, int n_in,
                              void* d_out, int out_size) {
    const float* xyz        = (const float*)d_in[0];
    const float* viewdirs   = (const float*)d_in[1];
    const float* transforms = (const float*)d_in[2];
    // d_in[3] = ray_valid — unused
    const float* sh_feats   = (const float*)d_in[4];
    const float* locs       = (const float*)d_in[5];
    float* out = (float*)d_out;

    int n = in_sizes[0] / 3;      // 524288
    int half = n / 2;             // 262144
    int threads = 256;
    int blocks = (half + threads - 1) / threads;
    shCaster_kernel<<<blocks, threads>>>(xyz, viewdirs, transforms, sh_feats,
                                         locs, out, half, n);
}